// round 15
// baseline (speedup 1.0000x reference)
#include <cuda_runtime.h>

// Problem constants
#define BB   4
#define CC   16
#define HH   64
#define WW   64
#define FF   32
#define K2   9

#define TILE_W   32     // pixels per block  -> grid 512 = single wave @4 CTA/SM
#define THREADS  256    // 8 warps: (c-half 0..1) x (px-quarter 0..3)
#define XCOLS    36     // 34 halo cols padded to 36 (16B-aligned rows)
#define NGRP     (CC * K2 + 1)   // +1 padding group for unconditional prefetch

// Repacked coefficients: [c][k][g][f] float4, one padding (k) group at the end
//   g=0: {n0,n1,n2,n3}   g=1: {n4,n5,d0,d1}   g=2: {d2,d3,0,0}
__device__ float4 g_coef4[NGRP * 3 * FF];

__device__ __forceinline__ float rcp_fast(float q) {
    float r; asm("rcp.approx.f32 %0, %1;" : "=f"(r) : "f"(q)); return r;
}
__device__ __forceinline__ float abs_bits(float v) {
    return __int_as_float(__float_as_int(v) & 0x7fffffff);
}

// ---------------------------------------------------------------------------
// Kernel 1: repack coefficients into [c][k][g][f] float4
// ---------------------------------------------------------------------------
__global__ void repack_coefs_kernel(const float* __restrict__ nums,
                                    const float* __restrict__ denoms) {
    int idx = blockIdx.x * blockDim.x + threadIdx.x;
    const int total = CC * K2 * 3 * FF;
    if (idx >= total) return;
    int f = idx & (FF - 1);
    int g = (idx >> 5) % 3;
    int k = (idx >> 5) / 3 % K2;
    int c = idx / (FF * 3 * K2);
    const float* np = nums   + (((f * CC + c) * K2) + k) * 6;
    const float* dp = denoms + (((f * CC + c) * K2) + k) * 4;
    float4 v;
    if (g == 0)      v = make_float4(np[0], np[1], np[2], np[3]);
    else if (g == 1) v = make_float4(np[4], np[5], dp[0], dp[1]);
    else             v = make_float4(dp[2], dp[3], 0.f, 0.f);
    g_coef4[idx] = v;
}

// ---------------------------------------------------------------------------
// Kernel 2: rational (Pade) conv.
//   grid  = (W/32, H, B) = (2, 64, 4) = 512 blocks, 256 threads (8 warps)
//   -> 3.46 CTA/SM at 4 resident = ONE wave, no tail quantization.
//   lane = f; warp -> (c-half: 8 channels, px-quarter: 8 pixels).
//   10 fma-pipe ops / eval: P Horner(5) + w Horner(3) + q=fma(|x|,|w|,1)(1)
//   + acc fma(1); |x| window via 12 LOP3 per (c,a) serving 24 evals.
//   Coefficients: linear prefetch cursor over padded [c][k][g][f] table.
//   2-way c reduction via smem, fixed order (deterministic).
// ---------------------------------------------------------------------------
__global__ __launch_bounds__(THREADS, 4)
void rational_conv_kernel(const float* __restrict__ x, float* __restrict__ out) {
    __shared__ __align__(16) float xs[CC][3][XCOLS];   // x halo tile, 6.75 KB
    __shared__ float red[4][32][9];                    // c-half-1 partials, pad 9

    const int wbase = blockIdx.x * TILE_W;
    const int h     = blockIdx.y;
    const int b     = blockIdx.z;
    const int tid   = threadIdx.x;
    const int lane  = tid & 31;            // f
    const int warp  = tid >> 5;            // 0..7
    const int chalf = warp >> 2;           // 0..1  (8 channels each)
    const int pxq   = warp & 3;            // 0..3  (8 pixels each)
    const int px0   = pxq * 8;

    // --- Load halo: 16 channels x 3 rows x 34 cols (wbase-1 .. wbase+32)
    for (int i = tid; i < CC * 3 * 34; i += THREADS) {
        int j  = i % 34;
        int r  = (i / 34) % 3;
        int c  = i / 102;
        int hh = h - 1 + r;
        int ww = wbase - 1 + j;
        float v = 0.0f;
        if (hh >= 0 && hh < HH && ww >= 0 && ww < WW)
            v = x[((b * CC + c) * HH + hh) * WW + ww];
        xs[c][r][j] = v;
    }
    __syncthreads();

    float acc[8];
    #pragma unroll
    for (int i = 0; i < 8; ++i) acc[i] = 0.0f;

    const int cstart = chalf * 8;

    // Linear coefficient cursor; prime with (c=cstart, k=0)
    const float4* cp = g_coef4 + (cstart * K2) * 3 * FF + lane;
    float4 A  = __ldg(cp);
    float4 Bv = __ldg(cp + FF);
    float4 Cv = __ldg(cp + 2 * FF);

    #pragma unroll 1
    for (int cc = 0; cc < 8; ++cc) {
        #pragma unroll
        for (int a = 0; a < 3; ++a) {
            // 12-float x window via 3 broadcast LDS.128 (px0 is 32B-aligned)
            const float* xrow = &xs[cstart + cc][a][px0];
            float4 xA = *reinterpret_cast<const float4*>(xrow);
            float4 xB = *reinterpret_cast<const float4*>(xrow + 4);
            float4 xC = *reinterpret_cast<const float4*>(xrow + 8);
            const float xw[12] = {xA.x, xA.y, xA.z, xA.w,
                                  xB.x, xB.y, xB.z, xB.w,
                                  xC.x, xC.y, xC.z, xC.w};
            // |x| window: 12 LOP3 serve 24 evals (0.5 alu/eval)
            float xa[12];
            #pragma unroll
            for (int j = 0; j < 12; ++j) xa[j] = abs_bits(xw[j]);

            #pragma unroll
            for (int bb = 0; bb < 3; ++bb) {
                // --- unconditional prefetch of next k-group (linear walk;
                //     final step reads the padding group, discarded)
                cp += 3 * FF;
                float4 An = __ldg(cp);
                float4 Bn = __ldg(cp + FF);
                float4 Cn = __ldg(cp + 2 * FF);

                const float n0 = A.x,  n1 = A.y,  n2 = A.z,  n3 = A.w;
                const float n4 = Bv.x, n5 = Bv.y, d0 = Bv.z, d1 = Bv.w;
                const float d2 = Cv.x, d3 = Cv.y;
                #pragma unroll
                for (int i = 0; i < 8; ++i) {
                    const float xv = xw[i + bb];
                    // P(x): Horner, 5 FMA
                    float p = fmaf(xv, n5, n4);
                    p = fmaf(xv, p, n3);
                    p = fmaf(xv, p, n2);
                    p = fmaf(xv, p, n1);
                    p = fmaf(xv, p, n0);
                    // w(x) = d0 + d1 x + d2 x^2 + d3 x^3: 3 FMA
                    float w = fmaf(xv, d3, d2);
                    w = fmaf(xv, w, d1);
                    w = fmaf(xv, w, d0);
                    // Q = 1 + |x*w| = fma(|x|, |w|, 1): 1 LOP3 + 1 FMA
                    const float q = fmaf(xa[i + bb], abs_bits(w), 1.0f);
                    acc[i] = fmaf(p, rcp_fast(q), acc[i]);
                }
                A = An; Bv = Bn; Cv = Cn;
            }
        }
    }

    // --- 2-way c reduction via smem, fixed order (deterministic)
    if (chalf == 1) {
        #pragma unroll
        for (int i = 0; i < 8; ++i) red[pxq][lane][i] = acc[i];
    }
    __syncthreads();
    if (chalf == 0) {
        #pragma unroll
        for (int i = 0; i < 8; ++i) acc[i] += red[pxq][lane][i];
        float* op = out + ((b * FF + lane) * HH + h) * WW + wbase + px0;
        *reinterpret_cast<float4*>(op)     = make_float4(acc[0], acc[1], acc[2], acc[3]);
        *reinterpret_cast<float4*>(op + 4) = make_float4(acc[4], acc[5], acc[6], acc[7]);
    }
}

// ---------------------------------------------------------------------------
// Launch
// ---------------------------------------------------------------------------
extern "C" void kernel_launch(void* const* d_in, const int* in_sizes, int n_in,
                              void* d_out, int out_size) {
    const float* x      = (const float*)d_in[0];   // (4,16,64,64)
    const float* nums   = (const float*)d_in[1];   // (32,16,3,3,6)
    const float* denoms = (const float*)d_in[2];   // (32,16,3,3,4)
    float* out = (float*)d_out;                    // (4,32,64,64)

    const int total = CC * K2 * 3 * FF;
    repack_coefs_kernel<<<(total + 255) / 256, 256>>>(nums, denoms);

    dim3 grid(WW / TILE_W, HH, BB);
    rational_conv_kernel<<<grid, THREADS>>>(x, out);
}

// round 16
// speedup vs baseline: 1.2895x; 1.2895x over previous
#include <cuda_runtime.h>

// Problem constants
#define BB   4
#define CC   16
#define HH   64
#define WW   64
#define FF   32
#define K2   9

#define TILE_W   16     // pixels per block
#define THREADS  128    // 4 warps: (c-half, px-half)  -- R10 proven geometry
#define XCOLS    20     // 18 halo cols padded to 20 (80B rows, 16B aligned)
#define NGRP     (CC * K2 + 1)   // +1 padding group for unconditional prefetch

// Repacked coefficients: [c][k][g][f] float4, one padding group at the end
//   g=0: {n0,n1,n2,n3}   g=1: {n4,n5,d0,d1}   g=2: {d2,d3,0,0}
__device__ float4 g_coef4[NGRP * 3 * FF];

__device__ __forceinline__ float rcp_fast(float q) {
    float r; asm("rcp.approx.f32 %0, %1;" : "=f"(r) : "f"(q)); return r;
}

// ---------------------------------------------------------------------------
// Kernel 1: repack coefficients into [c][k][g][f] float4.
// Signals programmatic completion IMMEDIATELY so the conv kernel's grid can
// launch and run its halo prologue concurrently; the conv kernel's
// cudaGridDependencySynchronize() still waits for our stores to be visible.
// ---------------------------------------------------------------------------
__global__ void repack_coefs_kernel(const float* __restrict__ nums,
                                    const float* __restrict__ denoms) {
#if __CUDA_ARCH__ >= 900
    cudaTriggerProgrammaticLaunchCompletion();
#endif
    int idx = blockIdx.x * blockDim.x + threadIdx.x;
    const int total = CC * K2 * 3 * FF;
    if (idx >= total) return;
    int f = idx & (FF - 1);
    int g = (idx >> 5) % 3;
    int k = (idx >> 5) / 3 % K2;
    int c = idx / (FF * 3 * K2);
    const float* np = nums   + (((f * CC + c) * K2) + k) * 6;
    const float* dp = denoms + (((f * CC + c) * K2) + k) * 4;
    float4 v;
    if (g == 0)      v = make_float4(np[0], np[1], np[2], np[3]);
    else if (g == 1) v = make_float4(np[4], np[5], dp[0], dp[1]);
    else             v = make_float4(dp[2], dp[3], 0.f, 0.f);
    g_coef4[idx] = v;
}

// ---------------------------------------------------------------------------
// Kernel 2: rational (Pade) conv — R10 proven form (11 fma-pipe ops/eval:
//   P Horner 5 + w Horner 3 + s=w*x 1 + q=1+|s| (FADD w/ free |src|) 1 +
//   acc fma 1), measured AT the fma-pipe roofline.
//   grid  = (4, 64, 4) = 1024 blocks, 128 threads (4 warps)
//   lane = f; warps 0/1 -> channels 0-7, warps 2/3 -> channels 8-15.
//   Coefficients: linear prefetch cursor over the padded [c][k][g][f] table.
//   PDL: halo load overlaps the repack kernel; grid-dependency sync before
//   the first coefficient read.
// ---------------------------------------------------------------------------
__global__ __launch_bounds__(THREADS, 7)
void rational_conv_kernel(const float* __restrict__ x, float* __restrict__ out) {
    __shared__ __align__(16) float xs[CC][3][XCOLS];   // 3.75 KB
    __shared__ float red[2][32][9];                    // partial sums, pad 9

    const int wbase = blockIdx.x * TILE_W;
    const int h     = blockIdx.y;
    const int b     = blockIdx.z;
    const int tid   = threadIdx.x;
    const int lane  = tid & 31;            // f
    const int warp  = tid >> 5;            // 0..3
    const int chalf = warp >> 1;           // 0..1
    const int pxw   = warp & 1;            // 0..1
    const int px0   = pxw * 8;

    // --- Load halo (independent of repack output -> runs under PDL overlap)
    for (int i = tid; i < CC * 3 * 18; i += THREADS) {
        int j  = i % 18;
        int r  = (i / 18) % 3;
        int c  = i / 54;
        int hh = h - 1 + r;
        int ww = wbase - 1 + j;
        float v = 0.0f;
        if (hh >= 0 && hh < HH && ww >= 0 && ww < WW)
            v = x[((b * CC + c) * HH + hh) * WW + ww];
        xs[c][r][j] = v;
    }
    __syncthreads();

#if __CUDA_ARCH__ >= 900
    // Wait for the repack kernel's stores before touching g_coef4.
    cudaGridDependencySynchronize();
#endif

    float acc[8];
    #pragma unroll
    for (int i = 0; i < 8; ++i) acc[i] = 0.0f;

    const int cstart = chalf * 8;

    // Linear coefficient cursor; prime with (c=cstart, k=0)
    const float4* cp = g_coef4 + (cstart * K2) * 3 * FF + lane;
    float4 A  = __ldg(cp);
    float4 Bv = __ldg(cp + FF);
    float4 Cv = __ldg(cp + 2 * FF);

    #pragma unroll 1
    for (int cc = 0; cc < 8; ++cc) {
        #pragma unroll
        for (int a = 0; a < 3; ++a) {
            // 12-float register window via 3 broadcast LDS.128
            const float* xrow = &xs[cstart + cc][a][px0];
            float4 xA = *reinterpret_cast<const float4*>(xrow);
            float4 xB = *reinterpret_cast<const float4*>(xrow + 4);
            float4 xC = *reinterpret_cast<const float4*>(xrow + 8);
            const float xw[12] = {xA.x, xA.y, xA.z, xA.w,
                                  xB.x, xB.y, xB.z, xB.w,
                                  xC.x, xC.y, xC.z, xC.w};
            #pragma unroll
            for (int bb = 0; bb < 3; ++bb) {
                // unconditional prefetch of next k-group (linear walk; final
                // step reads the padding group, discarded)
                cp += 3 * FF;
                float4 An = __ldg(cp);
                float4 Bn = __ldg(cp + FF);
                float4 Cn = __ldg(cp + 2 * FF);

                const float n0 = A.x,  n1 = A.y,  n2 = A.z,  n3 = A.w;
                const float n4 = Bv.x, n5 = Bv.y, d0 = Bv.z, d1 = Bv.w;
                const float d2 = Cv.x, d3 = Cv.y;
                #pragma unroll
                for (int i = 0; i < 8; ++i) {
                    const float xv = xw[i + bb];
                    // P(x): Horner, 5 FMA
                    float p = fmaf(xv, n5, n4);
                    p = fmaf(xv, p, n3);
                    p = fmaf(xv, p, n2);
                    p = fmaf(xv, p, n1);
                    p = fmaf(xv, p, n0);
                    // S(x) = x*(d0 + d1 x + d2 x^2 + d3 x^3)
                    float s = fmaf(xv, d3, d2);
                    s = fmaf(xv, s, d1);
                    s = fmaf(xv, s, d0);
                    s *= xv;
                    const float q = 1.0f + fabsf(s);   // |s| folds into FADD
                    acc[i] = fmaf(p, rcp_fast(q), acc[i]);
                }
                A = An; Bv = Bn; Cv = Cn;
            }
        }
    }

    // --- Combine the two c-halves via smem (deterministic 2-way add)
    if (chalf == 1) {
        #pragma unroll
        for (int i = 0; i < 8; ++i) red[pxw][lane][i] = acc[i];
    }
    __syncthreads();
    if (chalf == 0) {
        #pragma unroll
        for (int i = 0; i < 8; ++i) acc[i] += red[pxw][lane][i];
        float* op = out + ((b * FF + lane) * HH + h) * WW + wbase + px0;
        *reinterpret_cast<float4*>(op)     = make_float4(acc[0], acc[1], acc[2], acc[3]);
        *reinterpret_cast<float4*>(op + 4) = make_float4(acc[4], acc[5], acc[6], acc[7]);
    }
}

// ---------------------------------------------------------------------------
// Launch: repack, then conv with Programmatic Stream Serialization so the
// conv grid launches (and runs its halo prologue) while repack finishes.
// ---------------------------------------------------------------------------
extern "C" void kernel_launch(void* const* d_in, const int* in_sizes, int n_in,
                              void* d_out, int out_size) {
    const float* x      = (const float*)d_in[0];   // (4,16,64,64)
    const float* nums   = (const float*)d_in[1];   // (32,16,3,3,6)
    const float* denoms = (const float*)d_in[2];   // (32,16,3,3,4)
    float* out = (float*)d_out;                    // (4,32,64,64)

    const int total = CC * K2 * 3 * FF;
    repack_coefs_kernel<<<(total + 255) / 256, 256>>>(nums, denoms);

    cudaLaunchConfig_t cfg = {};
    cfg.gridDim  = dim3(WW / TILE_W, HH, BB);
    cfg.blockDim = dim3(THREADS, 1, 1);
    cfg.dynamicSmemBytes = 0;
    cfg.stream = 0;
    cudaLaunchAttribute attrs[1];
    attrs[0].id = cudaLaunchAttributeProgrammaticStreamSerialization;
    attrs[0].val.programmaticStreamSerializationAllowed = 1;
    cfg.attrs = attrs;
    cfg.numAttrs = 1;
    cudaLaunchKernelEx(&cfg, rational_conv_kernel, x, out);
}